// round 11
// baseline (speedup 1.0000x reference)
#include <cuda_runtime.h>
#include <cstdint>

// NeuralHMM forward, B=32, T=4096, K=16 — 3-phase chunked linear-space scan.
// Phase 1: blocks of 8 warps; warps 0-3 COMPOSE (2 chunks/warp via half-warps,
//   32-step serial chain, halfM snapshot at s=15), warps 4-7 WRITE A (pure
//   streaming, same chunks, no serial chain). Phase 2: per-batch depth-8 scan.
// Phase 3: replay at RC=16; odd sub-chunks apply the halfM matvec.

#define FULLM 0xffffffffu

constexpr int B_ = 32, T_ = 4096, K_ = 16;
constexpr int C_ = 32, NCH = T_ / C_;        // 128 chunks/batch
constexpr int NCHUNKS = B_ * NCH;            // 4096
constexpr int RC = 16, NSUB = T_ / RC;       // replay sub-chunks: 256/batch
constexpr int NSUB_TOT = B_ * NSUB;          // 8192
constexpr float RHO = 0.001f;
constexpr float D15 = 1.0f - RHO;            // 0.999
constexpr float CLIPV = 1e-10f;

__device__ __align__(16) float g_chunkM[NCHUNKS][K_][K_]; // [chunk][k][i] = M[i][k] (col-major)
__device__ __align__(16) float g_halfM[NCHUNKS][K_][K_];  // 16-step half matrix, same layout
__device__ __align__(16) float g_carry[NCHUNKS][K_];      // UNNORMALIZED alpha entering chunk j>=1

constexpr size_t N_BTK = (size_t)B_ * T_ * K_;
constexpr size_t N_BT  = (size_t)B_ * T_;
constexpr size_t OFF_LB = N_BTK;
constexpr size_t OFF_LZ = 2 * N_BTK;
constexpr size_t OFF_A  = 2 * N_BTK + N_BT;

// affine A coefficients for float4 slot j (row j>>2, cols (j&3)*4..+3):
// entry = K0 + eta*K1
__device__ __forceinline__ void slot_coeffs(int slot, float4& k0v, float4& k1v)
{
    const int r  = slot >> 2;
    const int c0 = (slot & 3) * 4;
    float k0[4], k1[4];
#pragma unroll
    for (int q = 0; q < 4; q++) {
        const int col = c0 + q;
        float a = 0.f, bcoef = 0.f;
        if (col == r - 1) a += RHO;
        if (col == r) {
            if (r == 0)       { a += 1.0f;       bcoef -= 1.0f; }
            else if (r == 15) { a += D15; }
            else              { a += 1.0f - RHO; bcoef -= 1.0f; }
        }
        if (col == r + 1 && r < 15) bcoef += 1.0f;
        k0[q] = a; k1[q] = bcoef;
    }
    k0v = make_float4(k0[0], k0[1], k0[2], k0[3]);
    k1v = make_float4(k1[0], k1[1], k1[2], k1[3]);
}

// ---------------------------------------------------------------------------
// Phase 1: 8-warp blocks. Warps 0-3: compose 8 chunks (2/warp, half-warps).
// Warps 4-7: stream the A tensor for the same 8 chunks (2/warp, full-warp
// coalesced stores, no serial chain).
// ---------------------------------------------------------------------------
__global__ __launch_bounds__(256) void k_chunkmats(
    const float* __restrict__ em, const float* __restrict__ bp,
    float* __restrict__ out)
{
    const int wid  = threadIdx.x >> 5;
    const int lane = threadIdx.x & 31;

    if (wid >= 4) {
        // ================= WRITER WARP =================
        const int w2 = wid - 4;
        const int c0 = (blockIdx.x * 4 + w2) * 2;     // chunks c0, c0+1
        float4 K0A, K1A, K0B, K1B;
        slot_coeffs(lane,      K0A, K1A);
        slot_coeffs(32 + lane, K0B, K1B);

#pragma unroll
        for (int cc = 0; cc < 2; cc++) {
            const int chunk = c0 + cc;
            const int b  = chunk >> 7;
            const int j  = chunk & (NCH - 1);
            const size_t bt0 = (size_t)b * T_ + j * C_;
            float4* __restrict__ A4 =
                reinterpret_cast<float4*>(out + OFF_A + bt0 * (size_t)(K_ * K_));
            const float bpv32 = __ldg(bp + bt0 + lane);   // lane = step

#pragma unroll 4
            for (int s = 0; s < C_; s++) {
                const float bpv = __shfl_sync(FULLM, bpv32, s);
                const float eta = fminf(fmaxf(fmaf(0.33f, bpv, 0.02f), 0.001f), 0.95f);
                float4 wa, wb;
                wa.x = fmaf(eta, K1A.x, K0A.x);
                wa.y = fmaf(eta, K1A.y, K0A.y);
                wa.z = fmaf(eta, K1A.z, K0A.z);
                wa.w = fmaf(eta, K1A.w, K0A.w);
                wb.x = fmaf(eta, K1B.x, K0B.x);
                wb.y = fmaf(eta, K1B.y, K0B.y);
                wb.z = fmaf(eta, K1B.z, K0B.z);
                wb.w = fmaf(eta, K1B.w, K0B.w);
                __stcs(A4 + s * 64 + lane, wa);
                __stcs(A4 + s * 64 + 32 + lane, wb);
            }
        }
        return;
    }

    // ================= COMPOSER WARP =================
    const int gwarp = blockIdx.x * 4 + wid;
    const int i     = lane & 15;
    const int chunk = gwarp * 2 + (lane >> 4);
    const unsigned hm = 0xffffu << (lane & 16);
    const int b  = chunk >> 7;           // /NCH (128)
    const int j  = chunk & (NCH - 1);
    const int t0 = j * C_;
    const size_t bt0 = (size_t)b * T_ + t0;

    const float* __restrict__ embase = em + bt0 * K_;

    // --- upfront bp (32 values per chunk via 2 regs + shfl) ---
    const float bpA = __ldg(bp + bt0 + i);
    const float bpB = __ldg(bp + bt0 + 16 + i);

    // --- em ring prefetch (lane's own k=i element), depth 4 ---
    float er[4];
#pragma unroll
    for (int u = 0; u < 4; u++) er[u] = __ldg(embase + u * K_ + i);

    float m[K_], mh[K_];
#pragma unroll
    for (int k = 0; k < K_; k++) { m[k] = (k == i) ? 1.0f : 0.0f; mh[k] = m[k]; }
    float rs = 1.0f;

#pragma unroll 4
    for (int s = 0; s < C_; s++) {
        const float emraw = er[s & 3];
        if (s + 4 < C_) er[s & 3] = __ldg(embase + (s + 4) * K_ + i);

        const float bpv = __shfl_sync(hm, (s < 16) ? bpA : bpB, s & 15, 16);
        const float eta = fminf(fmaxf(fmaf(0.33f, bpv, 0.02f), 0.001f), 0.95f);
        const float d0  = 1.0f - eta;
        const float dm  = d0 - RHO;

        // ---- compose (t=0 is init, not a transition) ----
        if (t0 + s > 0) {
            const float e_own = __expf(emraw);
            const float bg    = CLIPV * rs;   // background (rel err <= 3e-7)
            float rs_new = 0.0f, prev = 0.0f;
#pragma unroll
            for (int k = 0; k < 16; k++) {
                const float cur = m[k];
                const float nxt = (k < 15) ? m[k + 1] : 0.0f;
                float v;
                if (k == 0)       v = fmaf(cur, d0, bg);
                else if (k == 15) v = fmaf(prev, eta, fmaf(cur, D15, bg));
                else              v = fmaf(prev, eta, fmaf(cur, dm, bg));
                if (k < 15)       v = fmaf(nxt, RHO, v);
                v *= __shfl_sync(hm, e_own, k, 16);
                m[k] = v;
                rs_new += v;
                prev = cur;
            }
            rs = rs_new;
            if ((s & 7) == 7) {
                float mx = m[0];
#pragma unroll
                for (int k = 1; k < 16; k++) mx = fmaxf(mx, m[k]);
#pragma unroll
                for (int o = 1; o < 16; o <<= 1)
                    mx = fmaxf(mx, __shfl_xor_sync(hm, mx, o, 16));
                const float sc = __frcp_rn(mx);
#pragma unroll
                for (int k = 0; k < 16; k++) m[k] *= sc;
                rs *= sc;
            }
        }

        // ---- snapshot half matrix (state after step s=15) ----
        if (s == 15) {
#pragma unroll
            for (int k = 0; k < 16; k++) mh[k] = m[k];
        }
    }

    float* dstM = &g_chunkM[chunk][0][0];
    float* dstH = &g_halfM[chunk][0][0];
#pragma unroll
    for (int k = 0; k < 16; k++) {
        dstM[k * 16 + i] = m[k];
        dstH[k * 16 + i] = mh[k];
    }
}

// ---------------------------------------------------------------------------
// Phase 2: per-batch scan over 128 chunk matrices (one warp per batch).
// Depth-8 static software pipeline (covers L2 latency).
// ---------------------------------------------------------------------------
__device__ __forceinline__ float scan_hop(float v, const float4* c)
{
    float a0 = 0.f, a1 = 0.f, a2 = 0.f, a3 = 0.f;
    a0 = fmaf(__shfl_sync(FULLM, v, 0,  16), c[0].x, a0);
    a0 = fmaf(__shfl_sync(FULLM, v, 1,  16), c[0].y, a0);
    a0 = fmaf(__shfl_sync(FULLM, v, 2,  16), c[0].z, a0);
    a0 = fmaf(__shfl_sync(FULLM, v, 3,  16), c[0].w, a0);
    a1 = fmaf(__shfl_sync(FULLM, v, 4,  16), c[1].x, a1);
    a1 = fmaf(__shfl_sync(FULLM, v, 5,  16), c[1].y, a1);
    a1 = fmaf(__shfl_sync(FULLM, v, 6,  16), c[1].z, a1);
    a1 = fmaf(__shfl_sync(FULLM, v, 7,  16), c[1].w, a1);
    a2 = fmaf(__shfl_sync(FULLM, v, 8,  16), c[2].x, a2);
    a2 = fmaf(__shfl_sync(FULLM, v, 9,  16), c[2].y, a2);
    a2 = fmaf(__shfl_sync(FULLM, v, 10, 16), c[2].z, a2);
    a2 = fmaf(__shfl_sync(FULLM, v, 11, 16), c[2].w, a2);
    a3 = fmaf(__shfl_sync(FULLM, v, 12, 16), c[3].x, a3);
    a3 = fmaf(__shfl_sync(FULLM, v, 13, 16), c[3].y, a3);
    a3 = fmaf(__shfl_sync(FULLM, v, 14, 16), c[3].z, a3);
    a3 = fmaf(__shfl_sync(FULLM, v, 15, 16), c[3].w, a3);
    return (a0 + a1) + (a2 + a3);
}

#define SCAN_HOP_SLOT(S, J)                                                    \
    v = scan_hop(v, S);                                                        \
    if (lane < 16) carry[((J) + 1) * K_ + k] = v;                              \
    if ((J) + 8 < NCH) {                                                       \
        _Pragma("unroll")                                                      \
        for (int q = 0; q < 4; q++) S[q] = __ldg(base + ((J) + 8) * 64 + q);   \
    }

__global__ void k_scan()
{
    const int b    = blockIdx.x;
    const int lane = threadIdx.x;
    const int k    = lane & 15;

    const float4* __restrict__ base =
        reinterpret_cast<const float4*>(&g_chunkM[(size_t)b * NCH][0][0]) + k * 4;

    float4 s0[4], s1[4], s2[4], s3[4], s4[4], s5[4], s6[4], s7[4];
#pragma unroll
    for (int q = 0; q < 4; q++) {
        s0[q] = __ldg(base + 0 * 64 + q);
        s1[q] = __ldg(base + 1 * 64 + q);
        s2[q] = __ldg(base + 2 * 64 + q);
        s3[q] = __ldg(base + 3 * 64 + q);
        s4[q] = __ldg(base + 4 * 64 + q);
        s5[q] = __ldg(base + 5 * 64 + q);
        s6[q] = __ldg(base + 6 * 64 + q);
        s7[q] = __ldg(base + 7 * 64 + q);
    }

    float v = (k == 0) ? 1.0f : 0.0f;
    float* __restrict__ carry = &g_carry[(size_t)b * NCH][0];

    for (int jb = 0; jb < NCH; jb += 8) {
        SCAN_HOP_SLOT(s0, jb + 0)
        SCAN_HOP_SLOT(s1, jb + 1)
        SCAN_HOP_SLOT(s2, jb + 2)
        SCAN_HOP_SLOT(s3, jb + 3)
        SCAN_HOP_SLOT(s4, jb + 4)
        SCAN_HOP_SLOT(s5, jb + 5)
        SCAN_HOP_SLOT(s6, jb + 6)
        v = scan_hop(v, s7);
        if (jb + 8 < NCH) {
            if (lane < 16) carry[(jb + 8) * K_ + k] = v;
#pragma unroll
            for (int q = 0; q < 4; q++) s7[q] = __ldg(base + (jb + 15) * 64 + q);
        }
        float mx = v;
#pragma unroll
        for (int o = 1; o < 16; o <<= 1)
            mx = fmaxf(mx, __shfl_xor_sync(FULLM, mx, o, 16));
        v *= __frcp_rn(mx);
    }
}

// ---------------------------------------------------------------------------
// Phase 3: replay at RC=16. 2 sub-chunks/warp (half-warps), lane owns state k.
// Even sub-chunk 2p: carry = g_carry[p] (onehot for p=0). Odd sub-chunk 2p+1:
// carry = (p==0 ? onehot : g_carry[p]) * halfM[p]. Normalized on entry.
// ---------------------------------------------------------------------------
__global__ __launch_bounds__(128) void k_replay(
    const float* __restrict__ em, const float* __restrict__ bp,
    const float* __restrict__ msk, float* __restrict__ out)
{
    const int gwarp = (blockIdx.x * blockDim.x + threadIdx.x) >> 5;
    const int lane  = threadIdx.x & 31;
    const int k     = lane & 15;
    const int c     = gwarp * 2 + (lane >> 4);
    const unsigned hm = 0xffffu << (lane & 16);
    const int b  = c >> 8;               // /NSUB (256)
    const int jc = c & (NSUB - 1);
    const int pj = jc >> 1;              // parent chunk (C=32)
    const size_t bt0 = (size_t)b * T_ + jc * RC;

    float* __restrict__ bel = out;
    float* __restrict__ lgb = out + OFF_LB;
    float* __restrict__ lgz = out + OFF_LZ;

    const float* __restrict__ embase = em + bt0 * K_;

    const float bpv0 = __ldg(bp  + bt0 + k);
    const float mv0  = __ldg(msk + bt0 + k);

    float er[4];
#pragma unroll
    for (int u = 0; u < 4; u++) er[u] = __ldg(embase + u * K_ + k);

    float alpha;
    if (jc == 0) {
        alpha = (k == 0) ? 1.0f : 0.0f;
    } else {
        if (jc & 1) {
            // odd: alpha = carry(chunk pj) * halfM[pj]   (column k dot)
            const float v = (pj == 0) ? ((k == 0) ? 1.0f : 0.0f)
                                      : g_carry[b * NCH + pj][k];
            const float4* hc =
                reinterpret_cast<const float4*>(&g_halfM[b * NCH + pj][k][0]);
            const float4 c0 = __ldg(hc + 0), c1 = __ldg(hc + 1);
            const float4 c2 = __ldg(hc + 2), c3 = __ldg(hc + 3);
            float a0 = 0.f, a1 = 0.f, a2 = 0.f, a3 = 0.f;
            a0 = fmaf(__shfl_sync(hm, v, 0,  16), c0.x, a0);
            a0 = fmaf(__shfl_sync(hm, v, 1,  16), c0.y, a0);
            a0 = fmaf(__shfl_sync(hm, v, 2,  16), c0.z, a0);
            a0 = fmaf(__shfl_sync(hm, v, 3,  16), c0.w, a0);
            a1 = fmaf(__shfl_sync(hm, v, 4,  16), c1.x, a1);
            a1 = fmaf(__shfl_sync(hm, v, 5,  16), c1.y, a1);
            a1 = fmaf(__shfl_sync(hm, v, 6,  16), c1.z, a1);
            a1 = fmaf(__shfl_sync(hm, v, 7,  16), c1.w, a1);
            a2 = fmaf(__shfl_sync(hm, v, 8,  16), c2.x, a2);
            a2 = fmaf(__shfl_sync(hm, v, 9,  16), c2.y, a2);
            a2 = fmaf(__shfl_sync(hm, v, 10, 16), c2.z, a2);
            a2 = fmaf(__shfl_sync(hm, v, 11, 16), c2.w, a2);
            a3 = fmaf(__shfl_sync(hm, v, 12, 16), c3.x, a3);
            a3 = fmaf(__shfl_sync(hm, v, 13, 16), c3.y, a3);
            a3 = fmaf(__shfl_sync(hm, v, 14, 16), c3.z, a3);
            a3 = fmaf(__shfl_sync(hm, v, 15, 16), c3.w, a3);
            alpha = (a0 + a1) + (a2 + a3);
        } else {
            alpha = g_carry[b * NCH + pj][k];
        }
        float ss = alpha;
#pragma unroll
        for (int o = 1; o < 16; o <<= 1) ss += __shfl_xor_sync(hm, ss, o, 16);
        alpha *= __frcp_rn(ss);            // normalize: sum(alpha) == 1
    }

#pragma unroll 4
    for (int s = 0; s < RC; s++) {
        const float emv = er[s & 3];
        if (s + 4 < RC) er[s & 3] = __ldg(embase + (s + 4) * K_ + k);

        const size_t t = bt0 + s;
        const float bpv = __shfl_sync(hm, bpv0, s, 16);
        const float mv  = __shfl_sync(hm, mv0,  s, 16);

        if (s == 0 && jc == 0) {
            const float em00 = __shfl_sync(hm, emv, 0, 16);
            const float lb0 = (k == 0) ? 0.0f
                          : ((mv > 0.5f) ? ((-1.0e6f + emv) - em00) : -1.0e6f);
            bel[t * K_ + k] = alpha;
            lgb[t * K_ + k] = lb0;
            if (k == 0) lgz[t] = mv * em00;
            continue;
        }

        const float eta = fminf(fmaxf(fmaf(0.33f, bpv, 0.02f), 0.001f), 0.95f);
        const float d0  = 1.0f - eta;
        const float dm  = d0 - RHO;

        const float a_di = (k == 0) ? d0 : (k == 15 ? D15 : dm);

        const float am1 = __shfl_up_sync(hm, alpha, 1, 16);
        const float ap1 = __shfl_down_sync(hm, alpha, 1, 16);
        const float c_m1 = (k > 0)  ? am1 : 0.0f;
        const float c_p1 = (k < 15) ? ap1 : 0.0f;

        float pred = fmaf(c_m1, eta, CLIPV);       // background (sum(alpha)==1)
        pred = fmaf(alpha, a_di, pred);
        pred = fmaf(c_p1, RHO, pred);
        const float lj = pred * __expf(emv);

        float z = lj;
#pragma unroll
        for (int o = 1; o < 16; o <<= 1) z += __shfl_xor_sync(hm, z, o, 16);

        const float lZ = __logf(z);
        float lgbv;
        if (mv > 0.5f) {
            alpha = lj * __frcp_rn(z);
            lgbv  = __logf(alpha);
        } else {
            lgbv  = __logf(alpha);
        }

        bel[t * K_ + k] = alpha;
        lgb[t * K_ + k] = lgbv;
        if (k == 0) lgz[t] = mv * lZ;
    }
}

extern "C" void kernel_launch(void* const* d_in, const int* in_sizes, int n_in,
                              void* d_out, int out_size)
{
    const float* em  = (const float*)d_in[0];
    const float* bp  = (const float*)d_in[1];
    const float* msk = (const float*)d_in[2];
    float* out = (float*)d_out;

    k_chunkmats<<<512, 256>>>(em, bp, out);            // 8 warps: 4 compose + 4 write A
    k_scan<<<B_, 32>>>();
    k_replay<<<NSUB_TOT / 8, 128>>>(em, bp, msk, out); // 1024 blocks, RC=16
}

// round 12
// speedup vs baseline: 1.0809x; 1.0809x over previous
#include <cuda_runtime.h>
#include <cstdint>

// NeuralHMM forward, B=32, T=4096, K=16 — 3-phase chunked linear-space scan
// with the A-tensor write SPREAD across all three kernels (writer blocks
// co-scheduled after the critical-path blocks) to keep DRAM busy end-to-end.
//   k_compose : composer blocks (no A stores) + writers for steps [0,16)
//   k_scanA   : scan blocks + writers for steps [16,26)
//   k_replayA : replay blocks + writers for steps [26,32)

#define FULLM 0xffffffffu

constexpr int B_ = 32, T_ = 4096, K_ = 16;
constexpr int C_ = 32, NCH = T_ / C_;        // 128 chunks/batch
constexpr int NCHUNKS = B_ * NCH;            // 4096
constexpr int RC = 16, NSUB = T_ / RC;       // replay sub-chunks: 256/batch
constexpr int NSUB_TOT = B_ * NSUB;          // 8192
constexpr float RHO = 0.001f;
constexpr float D15 = 1.0f - RHO;            // 0.999
constexpr float CLIPV = 1e-10f;

__device__ __align__(16) float g_chunkM[NCHUNKS][K_][K_]; // [chunk][k][i] = M[i][k] (col-major)
__device__ __align__(16) float g_halfM[NCHUNKS][K_][K_];  // 16-step half matrix
__device__ __align__(16) float g_carry[NCHUNKS][K_];      // UNNORMALIZED alpha entering chunk j>=1

constexpr size_t N_BTK = (size_t)B_ * T_ * K_;
constexpr size_t N_BT  = (size_t)B_ * T_;
constexpr size_t OFF_LB = N_BTK;
constexpr size_t OFF_LZ = 2 * N_BTK;
constexpr size_t OFF_A  = 2 * N_BTK + N_BT;

// A-write step split across the three kernels
constexpr int SPLIT1 = 16;   // k_compose writes s in [0,16)
constexpr int SPLIT2 = 26;   // k_scanA   writes s in [16,26); k_replayA [26,32)

// affine A coefficients for float4 slot (row slot>>2, cols (slot&3)*4..+3):
// entry = K0 + eta*K1
__device__ __forceinline__ void slot_coeffs(int slot, float4& k0v, float4& k1v)
{
    const int r  = slot >> 2;
    const int c0 = (slot & 3) * 4;
    float k0[4], k1[4];
#pragma unroll
    for (int q = 0; q < 4; q++) {
        const int col = c0 + q;
        float a = 0.f, bcoef = 0.f;
        if (col == r - 1) a += RHO;
        if (col == r) {
            if (r == 0)       { a += 1.0f;       bcoef -= 1.0f; }
            else if (r == 15) { a += D15; }
            else              { a += 1.0f - RHO; bcoef -= 1.0f; }
        }
        if (col == r + 1 && r < 15) bcoef += 1.0f;
        k0[q] = a; k1[q] = bcoef;
    }
    k0v = make_float4(k0[0], k0[1], k0[2], k0[3]);
    k1v = make_float4(k1[0], k1[1], k1[2], k1[3]);
}

// One warp writes A for ONE chunk over steps [s_lo, s_hi). (R11-proven body)
__device__ __forceinline__ void write_A_range(
    int chunk, int s_lo, int s_hi, int lane,
    const float* __restrict__ bp, float* __restrict__ out)
{
    const int b = chunk >> 7;
    const int j = chunk & (NCH - 1);
    const size_t bt0 = (size_t)b * T_ + j * C_;
    float4* __restrict__ A4 =
        reinterpret_cast<float4*>(out + OFF_A + bt0 * (size_t)(K_ * K_));

    float4 K0A, K1A, K0B, K1B;
    slot_coeffs(lane,      K0A, K1A);
    slot_coeffs(32 + lane, K0B, K1B);

    const float bpv32 = __ldg(bp + bt0 + lane);   // lane = step index

    for (int s = s_lo; s < s_hi; s++) {
        const float bpv = __shfl_sync(FULLM, bpv32, s);
        const float eta = fminf(fmaxf(fmaf(0.33f, bpv, 0.02f), 0.001f), 0.95f);
        float4 wa, wb;
        wa.x = fmaf(eta, K1A.x, K0A.x);
        wa.y = fmaf(eta, K1A.y, K0A.y);
        wa.z = fmaf(eta, K1A.z, K0A.z);
        wa.w = fmaf(eta, K1A.w, K0A.w);
        wb.x = fmaf(eta, K1B.x, K0B.x);
        wb.y = fmaf(eta, K1B.y, K0B.y);
        wb.z = fmaf(eta, K1B.z, K0B.z);
        wb.w = fmaf(eta, K1B.w, K0B.w);
        __stcs(A4 + s * 64 + lane, wa);
        __stcs(A4 + s * 64 + 32 + lane, wb);
    }
}

// ---------------------------------------------------------------------------
// Kernel 1: blocks 0..511 compose (R10-proven, NO A stores); blocks 512..1535
// are writer blocks (4 warps, 1 chunk each) covering steps [0,16).
// ---------------------------------------------------------------------------
__global__ __launch_bounds__(128) void k_compose(
    const float* __restrict__ em, const float* __restrict__ bp,
    float* __restrict__ out)
{
    const int wid  = threadIdx.x >> 5;
    const int lane = threadIdx.x & 31;

    if (blockIdx.x >= 512) {
        const int chunk = (blockIdx.x - 512) * 4 + wid;   // 0..4095
        write_A_range(chunk, 0, SPLIT1, lane, bp, out);
        return;
    }

    // ================= COMPOSER =================
    const int gwarp = blockIdx.x * 4 + wid;
    const int i     = lane & 15;
    const int chunk = gwarp * 2 + (lane >> 4);
    const unsigned hm = 0xffffu << (lane & 16);
    const int b  = chunk >> 7;           // /NCH (128)
    const int j  = chunk & (NCH - 1);
    const int t0 = j * C_;
    const size_t bt0 = (size_t)b * T_ + t0;

    const float* __restrict__ embase = em + bt0 * K_;

    const float bpA = __ldg(bp + bt0 + i);
    const float bpB = __ldg(bp + bt0 + 16 + i);

    float er[4];
#pragma unroll
    for (int u = 0; u < 4; u++) er[u] = __ldg(embase + u * K_ + i);

    float m[K_], mh[K_];
#pragma unroll
    for (int k = 0; k < K_; k++) { m[k] = (k == i) ? 1.0f : 0.0f; mh[k] = m[k]; }
    float rs = 1.0f;

#pragma unroll 4
    for (int s = 0; s < C_; s++) {
        const float emraw = er[s & 3];
        if (s + 4 < C_) er[s & 3] = __ldg(embase + (s + 4) * K_ + i);

        const float bpv = __shfl_sync(hm, (s < 16) ? bpA : bpB, s & 15, 16);
        const float eta = fminf(fmaxf(fmaf(0.33f, bpv, 0.02f), 0.001f), 0.95f);
        const float d0  = 1.0f - eta;
        const float dm  = d0 - RHO;

        if (t0 + s > 0) {
            const float e_own = __expf(emraw);
            const float bg    = CLIPV * rs;   // background (rel err <= 3e-7)
            float rs_new = 0.0f, prev = 0.0f;
#pragma unroll
            for (int k = 0; k < 16; k++) {
                const float cur = m[k];
                const float nxt = (k < 15) ? m[k + 1] : 0.0f;
                float v;
                if (k == 0)       v = fmaf(cur, d0, bg);
                else if (k == 15) v = fmaf(prev, eta, fmaf(cur, D15, bg));
                else              v = fmaf(prev, eta, fmaf(cur, dm, bg));
                if (k < 15)       v = fmaf(nxt, RHO, v);
                v *= __shfl_sync(hm, e_own, k, 16);
                m[k] = v;
                rs_new += v;
                prev = cur;
            }
            rs = rs_new;
            if ((s & 7) == 7) {
                float mx = m[0];
#pragma unroll
                for (int k = 1; k < 16; k++) mx = fmaxf(mx, m[k]);
#pragma unroll
                for (int o = 1; o < 16; o <<= 1)
                    mx = fmaxf(mx, __shfl_xor_sync(hm, mx, o, 16));
                const float sc = __frcp_rn(mx);
#pragma unroll
                for (int k = 0; k < 16; k++) m[k] *= sc;
                rs *= sc;
            }
        }

        if (s == 15) {
#pragma unroll
            for (int k = 0; k < 16; k++) mh[k] = m[k];
        }
    }

    float* dstM = &g_chunkM[chunk][0][0];
    float* dstH = &g_halfM[chunk][0][0];
#pragma unroll
    for (int k = 0; k < 16; k++) {
        dstM[k * 16 + i] = m[k];
        dstH[k * 16 + i] = mh[k];
    }
}

// ---------------------------------------------------------------------------
// Kernel 2: blocks 0..31 scan (R7-proven, warp 0 of each block); blocks
// 32..1055 are writer blocks covering steps [16,26).
// ---------------------------------------------------------------------------
__device__ __forceinline__ float scan_hop(float v, const float4* c)
{
    float a0 = 0.f, a1 = 0.f, a2 = 0.f, a3 = 0.f;
    a0 = fmaf(__shfl_sync(FULLM, v, 0,  16), c[0].x, a0);
    a0 = fmaf(__shfl_sync(FULLM, v, 1,  16), c[0].y, a0);
    a0 = fmaf(__shfl_sync(FULLM, v, 2,  16), c[0].z, a0);
    a0 = fmaf(__shfl_sync(FULLM, v, 3,  16), c[0].w, a0);
    a1 = fmaf(__shfl_sync(FULLM, v, 4,  16), c[1].x, a1);
    a1 = fmaf(__shfl_sync(FULLM, v, 5,  16), c[1].y, a1);
    a1 = fmaf(__shfl_sync(FULLM, v, 6,  16), c[1].z, a1);
    a1 = fmaf(__shfl_sync(FULLM, v, 7,  16), c[1].w, a1);
    a2 = fmaf(__shfl_sync(FULLM, v, 8,  16), c[2].x, a2);
    a2 = fmaf(__shfl_sync(FULLM, v, 9,  16), c[2].y, a2);
    a2 = fmaf(__shfl_sync(FULLM, v, 10, 16), c[2].z, a2);
    a2 = fmaf(__shfl_sync(FULLM, v, 11, 16), c[2].w, a2);
    a3 = fmaf(__shfl_sync(FULLM, v, 12, 16), c[3].x, a3);
    a3 = fmaf(__shfl_sync(FULLM, v, 13, 16), c[3].y, a3);
    a3 = fmaf(__shfl_sync(FULLM, v, 14, 16), c[3].z, a3);
    a3 = fmaf(__shfl_sync(FULLM, v, 15, 16), c[3].w, a3);
    return (a0 + a1) + (a2 + a3);
}

#define SCAN_HOP_SLOT(S, J)                                                    \
    v = scan_hop(v, S);                                                        \
    if (lane < 16) carry[((J) + 1) * K_ + k] = v;                              \
    if ((J) + 8 < NCH) {                                                       \
        _Pragma("unroll")                                                      \
        for (int q = 0; q < 4; q++) S[q] = __ldg(base + ((J) + 8) * 64 + q);   \
    }

__global__ __launch_bounds__(128) void k_scanA(
    const float* __restrict__ bp, float* __restrict__ out)
{
    if (blockIdx.x >= 32) {
        const int wid  = threadIdx.x >> 5;
        const int lane = threadIdx.x & 31;
        const int chunk = (blockIdx.x - 32) * 4 + wid;   // 0..4095
        write_A_range(chunk, SPLIT1, SPLIT2, lane, bp, out);
        return;
    }
    if (threadIdx.x >= 32) return;

    const int b    = blockIdx.x;
    const int lane = threadIdx.x;
    const int k    = lane & 15;

    const float4* __restrict__ base =
        reinterpret_cast<const float4*>(&g_chunkM[(size_t)b * NCH][0][0]) + k * 4;

    float4 s0[4], s1[4], s2[4], s3[4], s4[4], s5[4], s6[4], s7[4];
#pragma unroll
    for (int q = 0; q < 4; q++) {
        s0[q] = __ldg(base + 0 * 64 + q);
        s1[q] = __ldg(base + 1 * 64 + q);
        s2[q] = __ldg(base + 2 * 64 + q);
        s3[q] = __ldg(base + 3 * 64 + q);
        s4[q] = __ldg(base + 4 * 64 + q);
        s5[q] = __ldg(base + 5 * 64 + q);
        s6[q] = __ldg(base + 6 * 64 + q);
        s7[q] = __ldg(base + 7 * 64 + q);
    }

    float v = (k == 0) ? 1.0f : 0.0f;
    float* __restrict__ carry = &g_carry[(size_t)b * NCH][0];

    for (int jb = 0; jb < NCH; jb += 8) {
        SCAN_HOP_SLOT(s0, jb + 0)
        SCAN_HOP_SLOT(s1, jb + 1)
        SCAN_HOP_SLOT(s2, jb + 2)
        SCAN_HOP_SLOT(s3, jb + 3)
        SCAN_HOP_SLOT(s4, jb + 4)
        SCAN_HOP_SLOT(s5, jb + 5)
        SCAN_HOP_SLOT(s6, jb + 6)
        v = scan_hop(v, s7);
        if (jb + 8 < NCH) {
            if (lane < 16) carry[(jb + 8) * K_ + k] = v;
#pragma unroll
            for (int q = 0; q < 4; q++) s7[q] = __ldg(base + (jb + 15) * 64 + q);
        }
        float mx = v;
#pragma unroll
        for (int o = 1; o < 16; o <<= 1)
            mx = fmaxf(mx, __shfl_xor_sync(FULLM, mx, o, 16));
        v *= __frcp_rn(mx);
    }
}

// ---------------------------------------------------------------------------
// Kernel 3: blocks 0..1023 replay (R10-proven, RC=16, 2 sub-chunks/warp);
// blocks 1024..2047 are writer blocks covering steps [26,32).
// ---------------------------------------------------------------------------
__global__ __launch_bounds__(128) void k_replayA(
    const float* __restrict__ em, const float* __restrict__ bp,
    const float* __restrict__ msk, float* __restrict__ out)
{
    if (blockIdx.x >= 1024) {
        const int wid  = threadIdx.x >> 5;
        const int lane = threadIdx.x & 31;
        const int chunk = (blockIdx.x - 1024) * 4 + wid;  // 0..4095
        write_A_range(chunk, SPLIT2, C_, lane, bp, out);
        return;
    }

    const int gwarp = (blockIdx.x * blockDim.x + threadIdx.x) >> 5;
    const int lane  = threadIdx.x & 31;
    const int k     = lane & 15;
    const int c     = gwarp * 2 + (lane >> 4);
    const unsigned hm = 0xffffu << (lane & 16);
    const int b  = c >> 8;               // /NSUB (256)
    const int jc = c & (NSUB - 1);
    const int pj = jc >> 1;              // parent chunk (C=32)
    const size_t bt0 = (size_t)b * T_ + jc * RC;

    float* __restrict__ bel = out;
    float* __restrict__ lgb = out + OFF_LB;
    float* __restrict__ lgz = out + OFF_LZ;

    const float* __restrict__ embase = em + bt0 * K_;

    const float bpv0 = __ldg(bp  + bt0 + k);
    const float mv0  = __ldg(msk + bt0 + k);

    float er[4];
#pragma unroll
    for (int u = 0; u < 4; u++) er[u] = __ldg(embase + u * K_ + k);

    float alpha;
    if (jc == 0) {
        alpha = (k == 0) ? 1.0f : 0.0f;
    } else {
        if (jc & 1) {
            // odd: alpha = carry(chunk pj) * halfM[pj]   (column k dot)
            const float v = (pj == 0) ? ((k == 0) ? 1.0f : 0.0f)
                                      : g_carry[b * NCH + pj][k];
            const float4* hc =
                reinterpret_cast<const float4*>(&g_halfM[b * NCH + pj][k][0]);
            const float4 c0 = __ldg(hc + 0), c1 = __ldg(hc + 1);
            const float4 c2 = __ldg(hc + 2), c3 = __ldg(hc + 3);
            float a0 = 0.f, a1 = 0.f, a2 = 0.f, a3 = 0.f;
            a0 = fmaf(__shfl_sync(hm, v, 0,  16), c0.x, a0);
            a0 = fmaf(__shfl_sync(hm, v, 1,  16), c0.y, a0);
            a0 = fmaf(__shfl_sync(hm, v, 2,  16), c0.z, a0);
            a0 = fmaf(__shfl_sync(hm, v, 3,  16), c0.w, a0);
            a1 = fmaf(__shfl_sync(hm, v, 4,  16), c1.x, a1);
            a1 = fmaf(__shfl_sync(hm, v, 5,  16), c1.y, a1);
            a1 = fmaf(__shfl_sync(hm, v, 6,  16), c1.z, a1);
            a1 = fmaf(__shfl_sync(hm, v, 7,  16), c1.w, a1);
            a2 = fmaf(__shfl_sync(hm, v, 8,  16), c2.x, a2);
            a2 = fmaf(__shfl_sync(hm, v, 9,  16), c2.y, a2);
            a2 = fmaf(__shfl_sync(hm, v, 10, 16), c2.z, a2);
            a2 = fmaf(__shfl_sync(hm, v, 11, 16), c2.w, a2);
            a3 = fmaf(__shfl_sync(hm, v, 12, 16), c3.x, a3);
            a3 = fmaf(__shfl_sync(hm, v, 13, 16), c3.y, a3);
            a3 = fmaf(__shfl_sync(hm, v, 14, 16), c3.z, a3);
            a3 = fmaf(__shfl_sync(hm, v, 15, 16), c3.w, a3);
            alpha = (a0 + a1) + (a2 + a3);
        } else {
            alpha = g_carry[b * NCH + pj][k];
        }
        float ss = alpha;
#pragma unroll
        for (int o = 1; o < 16; o <<= 1) ss += __shfl_xor_sync(hm, ss, o, 16);
        alpha *= __frcp_rn(ss);            // normalize: sum(alpha) == 1
    }

#pragma unroll 4
    for (int s = 0; s < RC; s++) {
        const float emv = er[s & 3];
        if (s + 4 < RC) er[s & 3] = __ldg(embase + (s + 4) * K_ + k);

        const size_t t = bt0 + s;
        const float bpv = __shfl_sync(hm, bpv0, s, 16);
        const float mv  = __shfl_sync(hm, mv0,  s, 16);

        if (s == 0 && jc == 0) {
            const float em00 = __shfl_sync(hm, emv, 0, 16);
            const float lb0 = (k == 0) ? 0.0f
                          : ((mv > 0.5f) ? ((-1.0e6f + emv) - em00) : -1.0e6f);
            bel[t * K_ + k] = alpha;
            lgb[t * K_ + k] = lb0;
            if (k == 0) lgz[t] = mv * em00;
            continue;
        }

        const float eta = fminf(fmaxf(fmaf(0.33f, bpv, 0.02f), 0.001f), 0.95f);
        const float d0  = 1.0f - eta;
        const float dm  = d0 - RHO;

        const float a_di = (k == 0) ? d0 : (k == 15 ? D15 : dm);

        const float am1 = __shfl_up_sync(hm, alpha, 1, 16);
        const float ap1 = __shfl_down_sync(hm, alpha, 1, 16);
        const float c_m1 = (k > 0)  ? am1 : 0.0f;
        const float c_p1 = (k < 15) ? ap1 : 0.0f;

        float pred = fmaf(c_m1, eta, CLIPV);       // background (sum(alpha)==1)
        pred = fmaf(alpha, a_di, pred);
        pred = fmaf(c_p1, RHO, pred);
        const float lj = pred * __expf(emv);

        float z = lj;
#pragma unroll
        for (int o = 1; o < 16; o <<= 1) z += __shfl_xor_sync(hm, z, o, 16);

        const float lZ = __logf(z);
        float lgbv;
        if (mv > 0.5f) {
            alpha = lj * __frcp_rn(z);
            lgbv  = __logf(alpha);
        } else {
            lgbv  = __logf(alpha);
        }

        bel[t * K_ + k] = alpha;
        lgb[t * K_ + k] = lgbv;
        if (k == 0) lgz[t] = mv * lZ;
    }
}

extern "C" void kernel_launch(void* const* d_in, const int* in_sizes, int n_in,
                              void* d_out, int out_size)
{
    const float* em  = (const float*)d_in[0];
    const float* bp  = (const float*)d_in[1];
    const float* msk = (const float*)d_in[2];
    float* out = (float*)d_out;

    k_compose<<<1536, 128>>>(em, bp, out);        // 512 compose + 1024 writer blocks
    k_scanA<<<1056, 128>>>(bp, out);              // 32 scan + 1024 writer blocks
    k_replayA<<<2048, 128>>>(em, bp, msk, out);   // 1024 replay + 1024 writer blocks
}